// round 9
// baseline (speedup 1.0000x reference)
#include <cuda_runtime.h>
#include <math.h>

// ---------------------------------------------------------------------------
// KANConvNet round 8: software-pipelined dense conv (double-buffered tap
// prefetch), PX=1 high-occupancy blocks, phi fused into pool epilogues.
// ---------------------------------------------------------------------------

#define NPIX0 (8 * 3 * 224 * 224)
#define NPIX1 (8 * 16 * 56 * 56)
#define NPIX2 (8 * 32 * 14 * 14)

__device__ float g_wp0[147 * 9 * 16];
__device__ float g_wp1[144 * 9 * 32];
__device__ float g_wp2[288 * 9 * 64];
__device__ float g_wpc[64  * 9 * 200];

__device__ float g_phi0[9 * NPIX0];
__device__ float g_a0[8 * 16 * 112 * 112];
__device__ float g_phi1[9 * NPIX1];
__device__ float g_part1[4 * 8 * 32 * 28 * 28];
__device__ float g_phi2[9 * NPIX2];
__device__ float g_part2[36 * 8 * 64 * 7 * 7];
__device__ float g_a2[8 * 64 * 7 * 7];

#define N0P (147 * 9 * 16)
#define N1P (144 * 9 * 32)
#define N2P (288 * 9 * 64)
#define NCP (64  * 9 * 200)

// ---------------- packed f32x2 helpers ----------------
__device__ __forceinline__ long long pk2(float a) {
    long long r;
    asm("mov.b64 %0, {%1, %1};" : "=l"(r) : "f"(a));
    return r;
}
__device__ __forceinline__ long long ffma2(long long a, long long b, long long c) {
    long long d;
    asm("fma.rn.f32x2 %0, %1, %2, %3;" : "=l"(d) : "l"(a), "l"(b), "l"(c));
    return d;
}
__device__ __forceinline__ float2 upk2(long long a) {
    float x, y;
    asm("mov.b64 {%0, %1}, %2;" : "=f"(x), "=f"(y) : "l"(a));
    return make_float2(x, y);
}

// ---------------- dense 9-coefficient evaluation ----------------
__device__ __forceinline__ void eval9(float x, float* c) {
    float sig = 1.0f / (1.0f + __expf(-x));
    c[0] = x * sig;
    float t  = fmaf(x, 2.5f, 5.5f);          // (x + 2.2) / 0.4
    float mf = floorf(t);
    bool inr = (mf >= 0.0f) && (mf <= 10.0f);
    mf = fminf(fmaxf(mf, 0.0f), 10.0f);
    float u  = t - mf;
    float u2 = u * u;
    float u3 = u2 * u;
    float om = 1.0f - u;
    const float s6 = 1.0f / 6.0f;
    float w0 = s6 * om * om * om;
    float w1 = s6 * fmaf(3.0f, u3, fmaf(-6.0f, u2, 4.0f));
    float w2 = s6 * fmaf(-3.0f, u3, fmaf(3.0f, u2, fmaf(3.0f, u, 1.0f)));
    float w3 = s6 * u3;
    int m = (int)mf;
#pragma unroll
    for (int r = 1; r < 9; r++) {
        int tt = (r - 1) - (m - 3);
        float cv = 0.0f;
        cv = (tt == 0) ? w0 : cv;
        cv = (tt == 1) ? w1 : cv;
        cv = (tt == 2) ? w2 : cv;
        cv = (tt == 3) ? w3 : cv;
        c[r] = inr ? cv : 0.0f;
    }
}

// eval5 (sparse) for the classifier head
__device__ __forceinline__ void eval5(float x, float& c0, float* w, int* r) {
    float sig = 1.0f / (1.0f + __expf(-x));
    c0 = x * sig;
    float t  = fmaf(x, 2.5f, 5.5f);
    float mf = floorf(t);
    bool inr = (mf >= 0.0f) && (mf <= 10.0f);
    mf = fminf(fmaxf(mf, 0.0f), 10.0f);
    float u  = t - mf;
    float u2 = u * u;
    float u3 = u2 * u;
    float om = 1.0f - u;
    const float s6 = 1.0f / 6.0f;
    float a0 = s6 * om * om * om;
    float a1 = s6 * fmaf(3.0f, u3, fmaf(-6.0f, u2, 4.0f));
    float a2 = s6 * fmaf(-3.0f, u3, fmaf(3.0f, u2, fmaf(3.0f, u, 1.0f)));
    float a3 = s6 * u3;
    int m = (int)mf;
    w[0] = (inr && m >= 3)            ? a0 : 0.0f;
    w[1] = (inr && m >= 2 && m <= 9)  ? a1 : 0.0f;
    w[2] = (inr && m >= 1 && m <= 8)  ? a2 : 0.0f;
    w[3] = (inr && m <= 7)            ? a3 : 0.0f;
#pragma unroll
    for (int t4 = 0; t4 < 4; t4++) {
        int j = m - 3 + t4;
        j = j < 0 ? 0 : (j > 7 ? 7 : j);
        r[t4] = 1 + j;
    }
}

// ---------------- phi precompute (layer 0 input only) ----------------
__global__ void phi_eval(const float* __restrict__ x, float* __restrict__ phi,
                         int n) {
    int i = blockIdx.x * blockDim.x + threadIdx.x;
    if (i >= n) return;
    float c[9];
    eval9(x[i], c);
#pragma unroll
    for (int r = 0; r < 9; r++) phi[r * n + i] = c[r];
}

// ---------------- merged weight packing ----------------
__device__ __forceinline__ void pack_one(int idx,
                                         const float* __restrict__ bw,
                                         const float* __restrict__ sw,
                                         const float* __restrict__ sc,
                                         float* __restrict__ wp,
                                         int OUT, int IN) {
    int i   = idx / (9 * OUT);
    int rem = idx - i * 9 * OUT;
    int r   = rem / OUT;
    int o   = rem - r * OUT;
    int oi  = o * IN + i;
    float v = (r == 0) ? bw[oi] : sw[oi * 8 + (r - 1)] * sc[oi];
    wp[idx] = v;
}

__global__ void pack_all(const float* bw0, const float* sw0, const float* sc0,
                         const float* bw1, const float* sw1, const float* sc1,
                         const float* bw2, const float* sw2, const float* sc2,
                         const float* bwc, const float* swc, const float* scc,
                         float* wp0, float* wp1, float* wp2, float* wpc) {
    int idx = blockIdx.x * blockDim.x + threadIdx.x;
    if (idx < N0P) { pack_one(idx, bw0, sw0, sc0, wp0, 16, 147); return; }
    idx -= N0P;
    if (idx < N1P) { pack_one(idx, bw1, sw1, sc1, wp1, 32, 144); return; }
    idx -= N1P;
    if (idx < N2P) { pack_one(idx, bw2, sw2, sc2, wp2, 64, 288); return; }
    idx -= N2P;
    if (idx < NCP) { pack_one(idx, bwc, swc, scc, wpc, 200, 64); }
}

// ---------------- inner-loop building blocks ----------------
__device__ __forceinline__ void ldtap(const float* __restrict__ phi, int npix,
                                      int idx, bool v, float* cr) {
#pragma unroll
    for (int r = 0; r < 9; r++) {
        const float PHI_PAD =
            (r == 3 || r == 6) ? (1.0f / 48.0f)
                               : ((r == 4 || r == 5) ? (23.0f / 48.0f) : 0.0f);
        cr[r] = v ? __ldg(phi + (long long)r * npix + idx) : PHI_PAD;
    }
}

// 16-output FMA step: wr points to [9][16] weight rows in smem.
__device__ __forceinline__ void fmastep16(const float* wr, const float* cr,
                                          long long* acc) {
#pragma unroll
    for (int r = 0; r < 9; r++) {
        const ulonglong2* wv = (const ulonglong2*)(wr + r * 16);
        long long cp = pk2(cr[r]);
#pragma unroll
        for (int q = 0; q < 4; q++) {
            ulonglong2 a = wv[q];
            acc[2 * q]     = ffma2(cp, (long long)a.x, acc[2 * q]);
            acc[2 * q + 1] = ffma2(cp, (long long)a.y, acc[2 * q + 1]);
        }
    }
}

// ---------------------------------------------------------------------------
// L0: K-chunked dense conv(7x7,s2), software-pipelined taps, PX=1.
// ---------------------------------------------------------------------------
template <int T>
__global__ void __launch_bounds__(T, 3)
kan_conv0(const float* __restrict__ phi,   // [9][NPIX0]
          const float* __restrict__ wp,    // [147][9][16]
          float* __restrict__ out) {       // (8,16,112,112) relu'd
    __shared__ float swm[49 * 9 * 16];     // 28224 B
    const int H = 224, W = 224, HW = H * W;

    const int N = 8 * 112 * 112;
    int gp     = blockIdx.x * T + threadIdx.x;
    bool valid = gp < N;
    int g  = valid ? gp : 0;
    int b  = g / (112 * 112);
    int rr = g - b * 112 * 112;
    int ho = rr / 112;
    int wo = rr - ho * 112;
    int hb = ho * 2 - 3;
    int wb = wo * 2 - 3;
    int pb = b * 3 * HW;

    long long acc[8];
#pragma unroll
    for (int k = 0; k < 8; k++) acc[k] = 0LL;

#pragma unroll 1
    for (int ch = 0; ch < 3; ch++) {
        __syncthreads();
        for (int idx = threadIdx.x; idx < 49 * 9 * 16; idx += T)
            swm[idx] = wp[ch * 49 * 9 * 16 + idx];
        __syncthreads();
        int cb = pb + ch * HW;

        float crA[9], crB[9];
        // prologue: load tap 0
        {
            int hin = hb, win = wb;
            bool v = valid && hin >= 0 && win >= 0;   // kh=kw=0
            ldtap(phi, NPIX0, cb + hin * W + win, v, crA);
        }
#pragma unroll 1
        for (int fl = 0; fl < 49; fl += 2) {
            // prefetch fl+1 into crB
            if (fl + 1 < 49) {
                int f2 = fl + 1;
                int kh = f2 / 7, kw = f2 - kh * 7;
                int hin = hb + kh, win = wb + kw;
                bool v = valid && hin >= 0 && hin < H && win >= 0 && win < W;
                ldtap(phi, NPIX0, cb + hin * W + win, v, crB);
            }
            fmastep16(swm + fl * 144, crA, acc);
            // prefetch fl+2 into crA
            if (fl + 2 < 49) {
                int f2 = fl + 2;
                int kh = f2 / 7, kw = f2 - kh * 7;
                int hin = hb + kh, win = wb + kw;
                bool v = valid && hin >= 0 && hin < H && win >= 0 && win < W;
                ldtap(phi, NPIX0, cb + hin * W + win, v, crA);
            }
            if (fl + 1 < 49) fmastep16(swm + (fl + 1) * 144, crB, acc);
        }
    }

    if (valid) {
        const long long OHW = 112 * 112;
        float* op = out + (long long)(b * 16) * OHW + rr;
#pragma unroll
        for (int k = 0; k < 8; k++) {
            float2 v = upk2(acc[k]);
            op[(2 * k) * OHW]     = fmaxf(v.x, 0.0f);
            op[(2 * k + 1) * OHW] = fmaxf(v.y, 0.0f);
        }
    }
}

// ---------------------------------------------------------------------------
// Dense gather-GEMM conv (K-sliced partials), software-pipelined, PX=1.
// ---------------------------------------------------------------------------
template <int CIN, int K, int S, int P, int OUT, int T, int FSL>
__global__ void __launch_bounds__(T, 3)
kan_conv_g(const float* __restrict__ phi,   // [9][B*CIN*H*W]
           const float* __restrict__ wp,    // [F][9][OUT]
           float* __restrict__ out,
           int B, int H, int W, int Ho, int Wo) {
    __shared__ float swm[FSL * 9 * 16];
    const int OT   = 16;
    const int NOT  = OUT / OT;
    const int sl   = blockIdx.y / NOT;
    const int ot   = blockIdx.y - sl * NOT;
    const int NPIX = B * CIN * H * W;

    for (int idx = threadIdx.x; idx < FSL * 9 * OT; idx += T) {
        int f   = idx / (9 * OT);
        int rem = idx - f * 9 * OT;
        int r   = rem / OT;
        int o   = rem - r * OT;
        swm[idx] = wp[((sl * FSL + f) * 9 + r) * OUT + ot * OT + o];
    }
    __syncthreads();

    const int N = B * Ho * Wo;
    int gp     = blockIdx.x * T + threadIdx.x;
    bool valid = gp < N;
    int g  = valid ? gp : 0;
    int b  = g / (Ho * Wo);
    int rr = g - b * Ho * Wo;
    int ho = rr / Wo;
    int wo = rr - ho * Wo;
    int hb = ho * S - P;
    int wb = wo * S - P;
    int pb = b * CIN * H * W;

    long long acc[8];
#pragma unroll
    for (int k = 0; k < 8; k++) acc[k] = 0LL;

    float crA[9], crB[9];
    {
        int f0  = sl * FSL;
        int c   = f0 / (K * K);
        int rem = f0 - c * K * K;
        int kh  = rem / K, kw = rem - kh * K;
        int hin = hb + kh, win = wb + kw;
        bool v = valid && hin >= 0 && hin < H && win >= 0 && win < W;
        ldtap(phi, NPIX, pb + (c * H + hin) * W + win, v, crA);
    }
#pragma unroll 1
    for (int fl = 0; fl < FSL; fl += 2) {
        if (fl + 1 < FSL) {
            int f2  = sl * FSL + fl + 1;
            int c   = f2 / (K * K);
            int rem = f2 - c * K * K;
            int kh  = rem / K, kw = rem - kh * K;
            int hin = hb + kh, win = wb + kw;
            bool v = valid && hin >= 0 && hin < H && win >= 0 && win < W;
            ldtap(phi, NPIX, pb + (c * H + hin) * W + win, v, crB);
        }
        fmastep16(swm + fl * 144, crA, acc);
        if (fl + 2 < FSL) {
            int f2  = sl * FSL + fl + 2;
            int c   = f2 / (K * K);
            int rem = f2 - c * K * K;
            int kh  = rem / K, kw = rem - kh * K;
            int hin = hb + kh, win = wb + kw;
            bool v = valid && hin >= 0 && hin < H && win >= 0 && win < W;
            ldtap(phi, NPIX, pb + (c * H + hin) * W + win, v, crA);
        }
        if (fl + 1 < FSL) fmastep16(swm + (fl + 1) * 144, crB, acc);
    }

    if (valid) {
        long long HW = (long long)Ho * Wo;
        float* op = out + (long long)sl * B * OUT * HW
                        + (long long)(b * OUT + ot * OT) * HW + rr;
#pragma unroll
        for (int k = 0; k < 8; k++) {
            float2 v = upk2(acc[k]);
            op[(2 * k) * HW]     = v.x;
            op[(2 * k + 1) * HW] = v.y;
        }
    }
}

// ---------------------------------------------------------------------------
// 2x2 max pool (relu'd input) fused with phi evaluation -> 9 planes
// ---------------------------------------------------------------------------
__global__ void maxpool2phi(const float* __restrict__ in, float* __restrict__ phi,
                            int B, int C, int H, int W) {
    int Ho = H / 2, Wo = W / 2;
    int n = B * C * Ho * Wo;
    int idx = blockIdx.x * blockDim.x + threadIdx.x;
    if (idx >= n) return;
    int wo = idx % Wo;
    int t  = idx / Wo;
    int ho = t % Ho;
    t /= Ho;
    int c = t % C;
    int b = t / C;
    const float* p = in + ((long long)(b * C + c) * H + ho * 2) * W + wo * 2;
    float m = fmaxf(fmaxf(p[0], p[1]), fmaxf(p[W], p[W + 1]));
    float cf[9];
    eval9(m, cf);
#pragma unroll
    for (int r = 0; r < 9; r++) phi[(long long)r * n + idx] = cf[r];
}

// ---------------------------------------------------------------------------
// sum NP partials -> relu -> 2x2 max pool -> phi
// ---------------------------------------------------------------------------
template <int NP>
__global__ void maxpool_sum_phi(const float* __restrict__ in,
                                float* __restrict__ phi,
                                int B, int C, int H, int W) {
    int Ho = H / 2, Wo = W / 2;
    int n = B * C * Ho * Wo;
    long long sz = (long long)B * C * H * W;
    int idx = blockIdx.x * blockDim.x + threadIdx.x;
    if (idx >= n) return;
    int wo = idx % Wo;
    int t  = idx / Wo;
    int ho = t % Ho;
    t /= Ho;
    int c = t % C;
    int b = t / C;
    long long base = ((long long)(b * C + c) * H + ho * 2) * W + wo * 2;
    float v[4] = {0.f, 0.f, 0.f, 0.f};
#pragma unroll
    for (int p = 0; p < NP; p++) {
        const float* ip = in + p * sz + base;
        v[0] += ip[0];
        v[1] += ip[1];
        v[2] += ip[W];
        v[3] += ip[W + 1];
    }
    float m = fmaxf(fmaxf(fmaxf(v[0], v[1]), fmaxf(v[2], v[3])), 0.0f);
    float cf[9];
    eval9(m, cf);
#pragma unroll
    for (int r = 0; r < 9; r++) phi[(long long)r * n + idx] = cf[r];
}

template <int NP>
__global__ void reduce_relu(const float* __restrict__ in, float* __restrict__ out,
                            int n) {
    int idx = blockIdx.x * blockDim.x + threadIdx.x;
    if (idx >= n) return;
    float s = 0.0f;
#pragma unroll
    for (int p = 0; p < NP; p++) s += in[(long long)p * n + idx];
    out[idx] = fmaxf(s, 0.0f);
}

// ---------------------------------------------------------------------------
// Head: mean(7x7) -> KAN linear 64 -> 200.
// ---------------------------------------------------------------------------
__global__ void classifier_kernel(const float* __restrict__ act,
                                  const float* __restrict__ wp,
                                  float* __restrict__ out) {
    __shared__ float mean[512];
    __shared__ float cs[512 * 5];
    __shared__ int   cr[512 * 4];
    int tid = threadIdx.x;
    int ot  = blockIdx.x;

    for (int e = tid; e < 512; e += 256) {
        const float* p = act + e * 49;
        float s = 0.0f;
#pragma unroll
        for (int i = 0; i < 49; i++) s += p[i];
        mean[e] = s * (1.0f / 49.0f);
    }
    __syncthreads();
    for (int e = tid; e < 512; e += 256) {
        float c0, w4[4];
        int   rw[4];
        eval5(mean[e], c0, w4, rw);
        cs[e * 5 + 0] = c0;
#pragma unroll
        for (int t = 0; t < 4; t++) {
            cs[e * 5 + 1 + t] = w4[t];
            cr[e * 4 + t]     = rw[t];
        }
    }
    __syncthreads();
    if (tid < 200) {
        int b = tid / 25;
        int o = ot * 25 + tid % 25;
        float acc = 0.0f;
#pragma unroll 4
        for (int i = 0; i < 64; i++) {
            int e = b * 64 + i;
            const float* cp = &cs[e * 5];
            const int*   rp = &cr[e * 4];
            const float* wr = wp + i * 9 * 200 + o;
            acc = fmaf(cp[0], wr[0], acc);
            acc = fmaf(cp[1], wr[rp[0] * 200], acc);
            acc = fmaf(cp[2], wr[rp[1] * 200], acc);
            acc = fmaf(cp[3], wr[rp[2] * 200], acc);
            acc = fmaf(cp[4], wr[rp[3] * 200], acc);
        }
        out[b * 200 + o] = acc;
    }
}

// ---------------------------------------------------------------------------
// Host launcher
// ---------------------------------------------------------------------------
static void* sym_addr(const void* symbol) {
    void* p = nullptr;
    cudaGetSymbolAddress(&p, symbol);
    return p;
}

extern "C" void kernel_launch(void* const* d_in, const int* in_sizes, int n_in,
                              void* d_out, int out_size) {
    const float* x   = (const float*)d_in[0];
    const float* bw0 = (const float*)d_in[1];
    const float* sw0 = (const float*)d_in[2];
    const float* sc0 = (const float*)d_in[3];
    const float* bw1 = (const float*)d_in[4];
    const float* sw1 = (const float*)d_in[5];
    const float* sc1 = (const float*)d_in[6];
    const float* bw2 = (const float*)d_in[7];
    const float* sw2 = (const float*)d_in[8];
    const float* sc2 = (const float*)d_in[9];
    const float* bwc = (const float*)d_in[10];
    const float* swc = (const float*)d_in[11];
    const float* scc = (const float*)d_in[12];
    float* out = (float*)d_out;

    float* wp0   = (float*)sym_addr(g_wp0);
    float* wp1   = (float*)sym_addr(g_wp1);
    float* wp2   = (float*)sym_addr(g_wp2);
    float* wpc   = (float*)sym_addr(g_wpc);
    float* phi0  = (float*)sym_addr(g_phi0);
    float* a0    = (float*)sym_addr(g_a0);
    float* phi1  = (float*)sym_addr(g_phi1);
    float* part1 = (float*)sym_addr(g_part1);
    float* phi2  = (float*)sym_addr(g_phi2);
    float* part2 = (float*)sym_addr(g_part2);
    float* a2    = (float*)sym_addr(g_a2);

    {
        int total = N0P + N1P + N2P + NCP;
        pack_all<<<(total + 255) / 256, 256>>>(bw0, sw0, sc0, bw1, sw1, sc1,
                                               bw2, sw2, sc2, bwc, swc, scc,
                                               wp0, wp1, wp2, wpc);
    }

    // ---- L0: phi -> pipelined K-chunked conv -> maxpool+phi ----
    phi_eval<<<(NPIX0 + 255) / 256, 256>>>(x, phi0, NPIX0);
    {
        const int T = 256;
        auto k = kan_conv0<T>;
        int grid = (8 * 112 * 112 + T - 1) / T;   // 392
        k<<<grid, T>>>(phi0, wp0, a0);
        maxpool2phi<<<(NPIX1 + 255) / 256, 256>>>(a0, phi1, 8, 16, 112, 112);
    }
    // ---- L1: 4 K-slices x 2 o-tiles -> partials -> pool+phi ----
    {
        auto k = kan_conv_g<16, 3, 2, 1, 32, 256, 36>;
        dim3 grid((8 * 28 * 28 + 255) / 256, 8);
        k<<<grid, 256>>>(phi1, wp1, part1, 8, 56, 56, 28, 28);
        maxpool_sum_phi<4><<<(NPIX2 + 255) / 256, 256>>>(part1, phi2, 8, 32, 28, 28);
    }
    // ---- L2: 36 K-slices x 4 o-tiles -> reduce_relu ----
    {
        auto k = kan_conv_g<32, 3, 2, 1, 64, 64, 8>;
        dim3 grid((8 * 7 * 7 + 63) / 64, 144);
        k<<<grid, 64>>>(phi2, wp2, part2, 8, 14, 14, 7, 7);
        reduce_relu<36><<<(8 * 64 * 7 * 7 + 255) / 256, 256>>>(part2, a2, 8 * 64 * 7 * 7);
    }
    classifier_kernel<<<8, 256>>>(a2, wpc, out);

    (void)in_sizes; (void)n_in; (void)out_size;
}

// round 10
// speedup vs baseline: 1.3182x; 1.3182x over previous
#include <cuda_runtime.h>
#include <math.h>

// ---------------------------------------------------------------------------
// KANConvNet round 9: revert to R5's measured-best conv structure
// (K-sliced dense gather-GEMM, PX=4, compiler-batched loads), with phi
// evaluation fused into the pool epilogues (removes p0/p1 round-trips).
// ---------------------------------------------------------------------------

#define NPIX0 (8 * 3 * 224 * 224)
#define NPIX1 (8 * 16 * 56 * 56)
#define NPIX2 (8 * 32 * 14 * 14)

__device__ float g_wp0[147 * 9 * 16];
__device__ float g_wp1[144 * 9 * 32];
__device__ float g_wp2[288 * 9 * 64];
__device__ float g_wpc[64  * 9 * 200];

__device__ float g_phi0[9 * NPIX0];
__device__ float g_part0[3 * 8 * 16 * 112 * 112];
__device__ float g_phi1[9 * NPIX1];
__device__ float g_part1[12 * 8 * 32 * 28 * 28];
__device__ float g_phi2[9 * NPIX2];
__device__ float g_part2[36 * 8 * 64 * 7 * 7];
__device__ float g_a2[8 * 64 * 7 * 7];

#define N0P (147 * 9 * 16)
#define N1P (144 * 9 * 32)
#define N2P (288 * 9 * 64)
#define NCP (64  * 9 * 200)

// ---------------- packed f32x2 helpers ----------------
__device__ __forceinline__ long long pk2(float a) {
    long long r;
    asm("mov.b64 %0, {%1, %1};" : "=l"(r) : "f"(a));
    return r;
}
__device__ __forceinline__ long long ffma2(long long a, long long b, long long c) {
    long long d;
    asm("fma.rn.f32x2 %0, %1, %2, %3;" : "=l"(d) : "l"(a), "l"(b), "l"(c));
    return d;
}
__device__ __forceinline__ float2 upk2(long long a) {
    float x, y;
    asm("mov.b64 {%0, %1}, %2;" : "=f"(x), "=f"(y) : "l"(a));
    return make_float2(x, y);
}

// ---------------- dense 9-coefficient evaluation ----------------
__device__ __forceinline__ void eval9(float x, float* c) {
    float sig = 1.0f / (1.0f + __expf(-x));
    c[0] = x * sig;
    float t  = fmaf(x, 2.5f, 5.5f);          // (x + 2.2) / 0.4
    float mf = floorf(t);
    bool inr = (mf >= 0.0f) && (mf <= 10.0f);
    mf = fminf(fmaxf(mf, 0.0f), 10.0f);
    float u  = t - mf;
    float u2 = u * u;
    float u3 = u2 * u;
    float om = 1.0f - u;
    const float s6 = 1.0f / 6.0f;
    float w0 = s6 * om * om * om;
    float w1 = s6 * fmaf(3.0f, u3, fmaf(-6.0f, u2, 4.0f));
    float w2 = s6 * fmaf(-3.0f, u3, fmaf(3.0f, u2, fmaf(3.0f, u, 1.0f)));
    float w3 = s6 * u3;
    int m = (int)mf;
#pragma unroll
    for (int r = 1; r < 9; r++) {
        int tt = (r - 1) - (m - 3);
        float cv = 0.0f;
        cv = (tt == 0) ? w0 : cv;
        cv = (tt == 1) ? w1 : cv;
        cv = (tt == 2) ? w2 : cv;
        cv = (tt == 3) ? w3 : cv;
        c[r] = inr ? cv : 0.0f;
    }
}

// eval5 (sparse) for the classifier head
__device__ __forceinline__ void eval5(float x, float& c0, float* w, int* r) {
    float sig = 1.0f / (1.0f + __expf(-x));
    c0 = x * sig;
    float t  = fmaf(x, 2.5f, 5.5f);
    float mf = floorf(t);
    bool inr = (mf >= 0.0f) && (mf <= 10.0f);
    mf = fminf(fmaxf(mf, 0.0f), 10.0f);
    float u  = t - mf;
    float u2 = u * u;
    float u3 = u2 * u;
    float om = 1.0f - u;
    const float s6 = 1.0f / 6.0f;
    float a0 = s6 * om * om * om;
    float a1 = s6 * fmaf(3.0f, u3, fmaf(-6.0f, u2, 4.0f));
    float a2 = s6 * fmaf(-3.0f, u3, fmaf(3.0f, u2, fmaf(3.0f, u, 1.0f)));
    float a3 = s6 * u3;
    int m = (int)mf;
    w[0] = (inr && m >= 3)            ? a0 : 0.0f;
    w[1] = (inr && m >= 2 && m <= 9)  ? a1 : 0.0f;
    w[2] = (inr && m >= 1 && m <= 8)  ? a2 : 0.0f;
    w[3] = (inr && m <= 7)            ? a3 : 0.0f;
#pragma unroll
    for (int t4 = 0; t4 < 4; t4++) {
        int j = m - 3 + t4;
        j = j < 0 ? 0 : (j > 7 ? 7 : j);
        r[t4] = 1 + j;
    }
}

// ---------------- phi precompute (layer-0 input only) ----------------
__global__ void phi_eval(const float* __restrict__ x, float* __restrict__ phi,
                         int n) {
    int i = blockIdx.x * blockDim.x + threadIdx.x;
    if (i >= n) return;
    float c[9];
    eval9(x[i], c);
#pragma unroll
    for (int r = 0; r < 9; r++) phi[r * n + i] = c[r];
}

// ---------------- merged weight packing ----------------
__device__ __forceinline__ void pack_one(int idx,
                                         const float* __restrict__ bw,
                                         const float* __restrict__ sw,
                                         const float* __restrict__ sc,
                                         float* __restrict__ wp,
                                         int OUT, int IN) {
    int i   = idx / (9 * OUT);
    int rem = idx - i * 9 * OUT;
    int r   = rem / OUT;
    int o   = rem - r * OUT;
    int oi  = o * IN + i;
    float v = (r == 0) ? bw[oi] : sw[oi * 8 + (r - 1)] * sc[oi];
    wp[idx] = v;
}

__global__ void pack_all(const float* bw0, const float* sw0, const float* sc0,
                         const float* bw1, const float* sw1, const float* sc1,
                         const float* bw2, const float* sw2, const float* sc2,
                         const float* bwc, const float* swc, const float* scc,
                         float* wp0, float* wp1, float* wp2, float* wpc) {
    int idx = blockIdx.x * blockDim.x + threadIdx.x;
    if (idx < N0P) { pack_one(idx, bw0, sw0, sc0, wp0, 16, 147); return; }
    idx -= N0P;
    if (idx < N1P) { pack_one(idx, bw1, sw1, sc1, wp1, 32, 144); return; }
    idx -= N1P;
    if (idx < N2P) { pack_one(idx, bw2, sw2, sc2, wp2, 64, 288); return; }
    idx -= N2P;
    if (idx < NCP) { pack_one(idx, bwc, swc, scc, wpc, 200, 64); }
}

// ---------------------------------------------------------------------------
// Dense gather-GEMM conv (K-sliced partials) — R5's measured-best kernel.
// ---------------------------------------------------------------------------
template <int CIN, int K, int S, int P, int OUT, int OT, int PX, int T, int FSL>
__global__ void __launch_bounds__(T, 3)
kan_conv_g(const float* __restrict__ phi,   // [9][B*CIN*H*W]
           const float* __restrict__ wp,    // [F][9][OUT]
           float* __restrict__ out,
           int B, int H, int W, int Ho, int Wo) {
    __shared__ float swm[FSL * 9 * OT];
    const int NOT  = OUT / OT;
    const int sl   = blockIdx.y / NOT;
    const int ot   = blockIdx.y - sl * NOT;
    const int NPIX = B * CIN * H * W;

    for (int idx = threadIdx.x; idx < FSL * 9 * OT; idx += T) {
        int f   = idx / (9 * OT);
        int rem = idx - f * 9 * OT;
        int r   = rem / OT;
        int o   = rem - r * OT;
        swm[idx] = wp[((sl * FSL + f) * 9 + r) * OUT + ot * OT + o];
    }
    __syncthreads();

    const float* pl[9];
#pragma unroll
    for (int r = 0; r < 9; r++) pl[r] = phi + (long long)r * NPIX;

    const float PHI_PAD[9] = {0.0f, 0.0f, 0.0f,
                              1.0f / 48.0f, 23.0f / 48.0f,
                              23.0f / 48.0f, 1.0f / 48.0f,
                              0.0f, 0.0f};

    const int N = B * Ho * Wo;
    int  hoS[PX], woS[PX], pbase[PX];
    bool pv[PX];
#pragma unroll
    for (int p = 0; p < PX; p++) {
        int gp = blockIdx.x * T * PX + p * T + threadIdx.x;
        pv[p]  = gp < N;
        int g  = pv[p] ? gp : 0;
        int b  = g / (Ho * Wo);
        int rr = g - b * Ho * Wo;
        int ho = rr / Wo;
        int wo = rr - ho * Wo;
        hoS[p]   = ho * S - P;
        woS[p]   = wo * S - P;
        pbase[p] = b * CIN * H * W;
    }

    long long acc[PX][OT / 2];
#pragma unroll
    for (int p = 0; p < PX; p++)
#pragma unroll
        for (int k = 0; k < OT / 2; k++) acc[p][k] = 0LL;

#pragma unroll 1
    for (int fl = 0; fl < FSL; fl++) {
        int f   = sl * FSL + fl;
        int c   = f / (K * K);
        int rem = f - c * K * K;
        int kh  = rem / K;
        int kw  = rem - kh * K;

        float cr[PX][9];
#pragma unroll
        for (int p = 0; p < PX; p++) {
            int hin = hoS[p] + kh;
            int win = woS[p] + kw;
            bool v  = pv[p] && (hin >= 0) && (hin < H) && (win >= 0) && (win < W);
            int idx = v ? (pbase[p] + (c * H + hin) * W + win) : 0;
#pragma unroll
            for (int r = 0; r < 9; r++)
                cr[p][r] = v ? __ldg(pl[r] + idx) : PHI_PAD[r];
        }

        const float* wr = swm + fl * 9 * OT;
#pragma unroll
        for (int r = 0; r < 9; r++) {
            const ulonglong2* wv = (const ulonglong2*)(wr + r * OT);
#pragma unroll
            for (int p = 0; p < PX; p++) {
                long long cp = pk2(cr[p][r]);
#pragma unroll
                for (int q = 0; q < OT / 4; q++) {
                    ulonglong2 a = wv[q];
                    acc[p][2 * q]     = ffma2(cp, (long long)a.x, acc[p][2 * q]);
                    acc[p][2 * q + 1] = ffma2(cp, (long long)a.y, acc[p][2 * q + 1]);
                }
            }
        }
    }

    long long HW = (long long)Ho * Wo;
    float* ob = out + (long long)sl * B * OUT * HW;
#pragma unroll
    for (int p = 0; p < PX; p++) {
        if (!pv[p]) continue;
        int gp = blockIdx.x * T * PX + p * T + threadIdx.x;
        int b  = gp / (Ho * Wo);
        int rr = gp - b * Ho * Wo;
        float* op = ob + (long long)(b * OUT + ot * OT) * HW + rr;
#pragma unroll
        for (int k = 0; k < OT / 2; k++) {
            float2 v = upk2(acc[p][k]);
            op[(2 * k) * HW]     = v.x;
            op[(2 * k + 1) * HW] = v.y;
        }
    }
}

// ---------------------------------------------------------------------------
// sum NP partials -> relu -> 2x2 max pool -> phi (9 planes)
// ---------------------------------------------------------------------------
template <int NP>
__global__ void maxpool_sum_phi(const float* __restrict__ in,
                                float* __restrict__ phi,
                                int B, int C, int H, int W) {
    int Ho = H / 2, Wo = W / 2;
    int n = B * C * Ho * Wo;
    long long sz = (long long)B * C * H * W;
    int idx = blockIdx.x * blockDim.x + threadIdx.x;
    if (idx >= n) return;
    int wo = idx % Wo;
    int t  = idx / Wo;
    int ho = t % Ho;
    t /= Ho;
    int c = t % C;
    int b = t / C;
    long long base = ((long long)(b * C + c) * H + ho * 2) * W + wo * 2;
    float v[4] = {0.f, 0.f, 0.f, 0.f};
#pragma unroll
    for (int p = 0; p < NP; p++) {
        const float* ip = in + p * sz + base;
        v[0] += ip[0];
        v[1] += ip[1];
        v[2] += ip[W];
        v[3] += ip[W + 1];
    }
    float m = fmaxf(fmaxf(fmaxf(v[0], v[1]), fmaxf(v[2], v[3])), 0.0f);
    float cf[9];
    eval9(m, cf);
#pragma unroll
    for (int r = 0; r < 9; r++) phi[(long long)r * n + idx] = cf[r];
}

template <int NP>
__global__ void reduce_relu(const float* __restrict__ in, float* __restrict__ out,
                            int n) {
    int idx = blockIdx.x * blockDim.x + threadIdx.x;
    if (idx >= n) return;
    float s = 0.0f;
#pragma unroll
    for (int p = 0; p < NP; p++) s += in[(long long)p * n + idx];
    out[idx] = fmaxf(s, 0.0f);
}

// ---------------------------------------------------------------------------
// Head: mean(7x7) -> KAN linear 64 -> 200.  8 blocks x 25 outputs.
// ---------------------------------------------------------------------------
__global__ void classifier_kernel(const float* __restrict__ act,
                                  const float* __restrict__ wp,
                                  float* __restrict__ out) {
    __shared__ float mean[512];
    __shared__ float cs[512 * 5];
    __shared__ int   cr[512 * 4];
    int tid = threadIdx.x;
    int ot  = blockIdx.x;

    for (int e = tid; e < 512; e += 256) {
        const float* p = act + e * 49;
        float s = 0.0f;
#pragma unroll
        for (int i = 0; i < 49; i++) s += p[i];
        mean[e] = s * (1.0f / 49.0f);
    }
    __syncthreads();
    for (int e = tid; e < 512; e += 256) {
        float c0, w4[4];
        int   rw[4];
        eval5(mean[e], c0, w4, rw);
        cs[e * 5 + 0] = c0;
#pragma unroll
        for (int t = 0; t < 4; t++) {
            cs[e * 5 + 1 + t] = w4[t];
            cr[e * 4 + t]     = rw[t];
        }
    }
    __syncthreads();
    if (tid < 200) {
        int b = tid / 25;
        int o = ot * 25 + tid % 25;
        float acc = 0.0f;
#pragma unroll 4
        for (int i = 0; i < 64; i++) {
            int e = b * 64 + i;
            const float* cp = &cs[e * 5];
            const int*   rp = &cr[e * 4];
            const float* wr = wp + i * 9 * 200 + o;
            acc = fmaf(cp[0], wr[0], acc);
            acc = fmaf(cp[1], wr[rp[0] * 200], acc);
            acc = fmaf(cp[2], wr[rp[1] * 200], acc);
            acc = fmaf(cp[3], wr[rp[2] * 200], acc);
            acc = fmaf(cp[4], wr[rp[3] * 200], acc);
        }
        out[b * 200 + o] = acc;
    }
}

// ---------------------------------------------------------------------------
// Host launcher
// ---------------------------------------------------------------------------
static void* sym_addr(const void* symbol) {
    void* p = nullptr;
    cudaGetSymbolAddress(&p, symbol);
    return p;
}

extern "C" void kernel_launch(void* const* d_in, const int* in_sizes, int n_in,
                              void* d_out, int out_size) {
    const float* x   = (const float*)d_in[0];
    const float* bw0 = (const float*)d_in[1];
    const float* sw0 = (const float*)d_in[2];
    const float* sc0 = (const float*)d_in[3];
    const float* bw1 = (const float*)d_in[4];
    const float* sw1 = (const float*)d_in[5];
    const float* sc1 = (const float*)d_in[6];
    const float* bw2 = (const float*)d_in[7];
    const float* sw2 = (const float*)d_in[8];
    const float* sc2 = (const float*)d_in[9];
    const float* bwc = (const float*)d_in[10];
    const float* swc = (const float*)d_in[11];
    const float* scc = (const float*)d_in[12];
    float* out = (float*)d_out;

    float* wp0   = (float*)sym_addr(g_wp0);
    float* wp1   = (float*)sym_addr(g_wp1);
    float* wp2   = (float*)sym_addr(g_wp2);
    float* wpc   = (float*)sym_addr(g_wpc);
    float* phi0  = (float*)sym_addr(g_phi0);
    float* part0 = (float*)sym_addr(g_part0);
    float* phi1  = (float*)sym_addr(g_phi1);
    float* part1 = (float*)sym_addr(g_part1);
    float* phi2  = (float*)sym_addr(g_phi2);
    float* part2 = (float*)sym_addr(g_part2);
    float* a2    = (float*)sym_addr(g_a2);

    {
        int total = N0P + N1P + N2P + NCP;
        pack_all<<<(total + 255) / 256, 256>>>(bw0, sw0, sc0, bw1, sw1, sc1,
                                               bw2, sw2, sc2, bwc, swc, scc,
                                               wp0, wp1, wp2, wpc);
    }

    // ---- L0: phi -> R5 conv (196x3 blocks, PX=4) -> pool+phi ----
    phi_eval<<<(NPIX0 + 255) / 256, 256>>>(x, phi0, NPIX0);
    {
        auto k = kan_conv_g<3, 7, 2, 3, 16, 16, 4, 128, 49>;
        dim3 grid(196, 3);
        k<<<grid, 128>>>(phi0, wp0, part0, 8, 224, 224, 112, 112);
        maxpool_sum_phi<3><<<(NPIX1 + 255) / 256, 256>>>(part0, phi1, 8, 16, 112, 112);
    }
    // ---- L1: 12 K-slices x 2 o-tiles (R5 shape) -> pool+phi ----
    {
        auto k = kan_conv_g<16, 3, 2, 1, 32, 16, 4, 128, 12>;
        dim3 grid(13, 24);
        k<<<grid, 128>>>(phi1, wp1, part1, 8, 56, 56, 28, 28);
        maxpool_sum_phi<12><<<(NPIX2 + 255) / 256, 256>>>(part1, phi2, 8, 32, 28, 28);
    }
    // ---- L2: 36 K-slices x 4 o-tiles (R5 shape) -> reduce_relu ----
    {
        auto k = kan_conv_g<32, 3, 2, 1, 64, 16, 1, 128, 8>;
        dim3 grid(4, 144);
        k<<<grid, 128>>>(phi2, wp2, part2, 8, 14, 14, 7, 7);
        reduce_relu<36><<<(8 * 64 * 7 * 7 + 255) / 256, 256>>>(part2, a2, 8 * 64 * 7 * 7);
    }
    classifier_kernel<<<8, 256>>>(a2, wpc, out);

    (void)in_sizes; (void)n_in; (void)out_size;
}

// round 11
// speedup vs baseline: 1.3711x; 1.0401x over previous
#include <cuda_runtime.h>
#include <math.h>

// ---------------------------------------------------------------------------
// KANConvNet round 10: R9 structure (K-sliced dense gather-GEMM, PX=4,
// fused pool+phi epilogues) with:
//   (a) phi packed as 5 float2 SoA planes  (9 LDG.32 -> 5 LDG.64 per tap)
//   (b) incremental (c,kh,kw) tap counters (no per-iter divisions)
// ---------------------------------------------------------------------------

#define NPIX0 (8 * 3 * 224 * 224)
#define NPIX1 (8 * 16 * 56 * 56)
#define NPIX2 (8 * 32 * 14 * 14)

__device__ float g_wp0[147 * 9 * 16];
__device__ float g_wp1[144 * 9 * 32];
__device__ float g_wp2[288 * 9 * 64];
__device__ float g_wpc[64  * 9 * 200];

__device__ float2 g_phi0[5 * NPIX0];
__device__ float  g_part0[3 * 8 * 16 * 112 * 112];
__device__ float2 g_phi1[5 * NPIX1];
__device__ float  g_part1[12 * 8 * 32 * 28 * 28];
__device__ float2 g_phi2[5 * NPIX2];
__device__ float  g_part2[36 * 8 * 64 * 7 * 7];
__device__ float  g_a2[8 * 64 * 7 * 7];

#define N0P (147 * 9 * 16)
#define N1P (144 * 9 * 32)
#define N2P (288 * 9 * 64)
#define NCP (64  * 9 * 200)

// ---------------- packed f32x2 helpers ----------------
__device__ __forceinline__ long long pk2(float a) {
    long long r;
    asm("mov.b64 %0, {%1, %1};" : "=l"(r) : "f"(a));
    return r;
}
__device__ __forceinline__ long long ffma2(long long a, long long b, long long c) {
    long long d;
    asm("fma.rn.f32x2 %0, %1, %2, %3;" : "=l"(d) : "l"(a), "l"(b), "l"(c));
    return d;
}
__device__ __forceinline__ float2 upk2(long long a) {
    float x, y;
    asm("mov.b64 {%0, %1}, %2;" : "=f"(x), "=f"(y) : "l"(a));
    return make_float2(x, y);
}

// ---------------- dense 9-coefficient evaluation ----------------
__device__ __forceinline__ void eval9(float x, float* c) {
    float sig = 1.0f / (1.0f + __expf(-x));
    c[0] = x * sig;
    float t  = fmaf(x, 2.5f, 5.5f);          // (x + 2.2) / 0.4
    float mf = floorf(t);
    bool inr = (mf >= 0.0f) && (mf <= 10.0f);
    mf = fminf(fmaxf(mf, 0.0f), 10.0f);
    float u  = t - mf;
    float u2 = u * u;
    float u3 = u2 * u;
    float om = 1.0f - u;
    const float s6 = 1.0f / 6.0f;
    float w0 = s6 * om * om * om;
    float w1 = s6 * fmaf(3.0f, u3, fmaf(-6.0f, u2, 4.0f));
    float w2 = s6 * fmaf(-3.0f, u3, fmaf(3.0f, u2, fmaf(3.0f, u, 1.0f)));
    float w3 = s6 * u3;
    int m = (int)mf;
#pragma unroll
    for (int r = 1; r < 9; r++) {
        int tt = (r - 1) - (m - 3);
        float cv = 0.0f;
        cv = (tt == 0) ? w0 : cv;
        cv = (tt == 1) ? w1 : cv;
        cv = (tt == 2) ? w2 : cv;
        cv = (tt == 3) ? w3 : cv;
        c[r] = inr ? cv : 0.0f;
    }
}

// eval5 (sparse) for the classifier head
__device__ __forceinline__ void eval5(float x, float& c0, float* w, int* r) {
    float sig = 1.0f / (1.0f + __expf(-x));
    c0 = x * sig;
    float t  = fmaf(x, 2.5f, 5.5f);
    float mf = floorf(t);
    bool inr = (mf >= 0.0f) && (mf <= 10.0f);
    mf = fminf(fmaxf(mf, 0.0f), 10.0f);
    float u  = t - mf;
    float u2 = u * u;
    float u3 = u2 * u;
    float om = 1.0f - u;
    const float s6 = 1.0f / 6.0f;
    float a0 = s6 * om * om * om;
    float a1 = s6 * fmaf(3.0f, u3, fmaf(-6.0f, u2, 4.0f));
    float a2 = s6 * fmaf(-3.0f, u3, fmaf(3.0f, u2, fmaf(3.0f, u, 1.0f)));
    float a3 = s6 * u3;
    int m = (int)mf;
    w[0] = (inr && m >= 3)            ? a0 : 0.0f;
    w[1] = (inr && m >= 2 && m <= 9)  ? a1 : 0.0f;
    w[2] = (inr && m >= 1 && m <= 8)  ? a2 : 0.0f;
    w[3] = (inr && m <= 7)            ? a3 : 0.0f;
#pragma unroll
    for (int t4 = 0; t4 < 4; t4++) {
        int j = m - 3 + t4;
        j = j < 0 ? 0 : (j > 7 ? 7 : j);
        r[t4] = 1 + j;
    }
}

// store 9 coefficients as 5 float2 planes
__device__ __forceinline__ void store_phi_pairs(float2* __restrict__ phi,
                                                long long n, long long i,
                                                const float* c) {
    phi[0 * n + i] = make_float2(c[0], c[1]);
    phi[1 * n + i] = make_float2(c[2], c[3]);
    phi[2 * n + i] = make_float2(c[4], c[5]);
    phi[3 * n + i] = make_float2(c[6], c[7]);
    phi[4 * n + i] = make_float2(c[8], 0.0f);
}

// ---------------- phi precompute (layer-0 input only) ----------------
__global__ void phi_eval(const float* __restrict__ x, float2* __restrict__ phi,
                         int n) {
    int i = blockIdx.x * blockDim.x + threadIdx.x;
    if (i >= n) return;
    float c[9];
    eval9(x[i], c);
    store_phi_pairs(phi, n, i, c);
}

// ---------------- merged weight packing ----------------
__device__ __forceinline__ void pack_one(int idx,
                                         const float* __restrict__ bw,
                                         const float* __restrict__ sw,
                                         const float* __restrict__ sc,
                                         float* __restrict__ wp,
                                         int OUT, int IN) {
    int i   = idx / (9 * OUT);
    int rem = idx - i * 9 * OUT;
    int r   = rem / OUT;
    int o   = rem - r * OUT;
    int oi  = o * IN + i;
    float v = (r == 0) ? bw[oi] : sw[oi * 8 + (r - 1)] * sc[oi];
    wp[idx] = v;
}

__global__ void pack_all(const float* bw0, const float* sw0, const float* sc0,
                         const float* bw1, const float* sw1, const float* sc1,
                         const float* bw2, const float* sw2, const float* sc2,
                         const float* bwc, const float* swc, const float* scc,
                         float* wp0, float* wp1, float* wp2, float* wpc) {
    int idx = blockIdx.x * blockDim.x + threadIdx.x;
    if (idx < N0P) { pack_one(idx, bw0, sw0, sc0, wp0, 16, 147); return; }
    idx -= N0P;
    if (idx < N1P) { pack_one(idx, bw1, sw1, sc1, wp1, 32, 144); return; }
    idx -= N1P;
    if (idx < N2P) { pack_one(idx, bw2, sw2, sc2, wp2, 64, 288); return; }
    idx -= N2P;
    if (idx < NCP) { pack_one(idx, bwc, swc, scc, wpc, 200, 64); }
}

// ---------------------------------------------------------------------------
// Dense gather-GEMM conv (K-sliced partials), float2 phi, incremental taps.
// ---------------------------------------------------------------------------
template <int CIN, int K, int S, int P, int OUT, int OT, int PX, int T, int FSL>
__global__ void __launch_bounds__(T, 3)
kan_conv_g(const float2* __restrict__ phi,  // [5][B*CIN*H*W] pairs
           const float* __restrict__ wp,    // [F][9][OUT]
           float* __restrict__ out,
           int B, int H, int W, int Ho, int Wo) {
    __shared__ float swm[FSL * 9 * OT];
    const int NOT  = OUT / OT;
    const int sl   = blockIdx.y / NOT;
    const int ot   = blockIdx.y - sl * NOT;
    const int NPIX = B * CIN * H * W;

    for (int idx = threadIdx.x; idx < FSL * 9 * OT; idx += T) {
        int f   = idx / (9 * OT);
        int rem = idx - f * 9 * OT;
        int r   = rem / OT;
        int o   = rem - r * OT;
        swm[idx] = wp[((sl * FSL + f) * 9 + r) * OUT + ot * OT + o];
    }
    __syncthreads();

    const float2* pl[5];
#pragma unroll
    for (int r = 0; r < 5; r++) pl[r] = phi + (long long)r * NPIX;

    const float2 PHI_PAD[5] = {
        make_float2(0.0f, 0.0f),
        make_float2(0.0f, 1.0f / 48.0f),
        make_float2(23.0f / 48.0f, 23.0f / 48.0f),
        make_float2(1.0f / 48.0f, 0.0f),
        make_float2(0.0f, 0.0f)};

    const int N = B * Ho * Wo;
    int  hoS[PX], woS[PX], pbase[PX];
    bool pv[PX];
#pragma unroll
    for (int p = 0; p < PX; p++) {
        int gp = blockIdx.x * T * PX + p * T + threadIdx.x;
        pv[p]  = gp < N;
        int g  = pv[p] ? gp : 0;
        int b  = g / (Ho * Wo);
        int rr = g - b * Ho * Wo;
        int ho = rr / Wo;
        int wo = rr - ho * Wo;
        hoS[p]   = ho * S - P;
        woS[p]   = wo * S - P;
        pbase[p] = b * CIN * H * W;
    }

    long long acc[PX][OT / 2];
#pragma unroll
    for (int p = 0; p < PX; p++)
#pragma unroll
        for (int k = 0; k < OT / 2; k++) acc[p][k] = 0LL;

    // incremental tap decode (uniform across block)
    int f0 = sl * FSL;
    int c  = f0 / (K * K);
    int r0 = f0 - c * K * K;
    int kh = r0 / K;
    int kw = r0 - kh * K;

#pragma unroll 1
    for (int fl = 0; fl < FSL; fl++) {
        float2 cr[PX][5];
#pragma unroll
        for (int p = 0; p < PX; p++) {
            int hin = hoS[p] + kh;
            int win = woS[p] + kw;
            bool v  = pv[p] && (hin >= 0) && (hin < H) && (win >= 0) && (win < W);
            int idx = v ? (pbase[p] + (c * H + hin) * W + win) : 0;
#pragma unroll
            for (int r = 0; r < 5; r++)
                cr[p][r] = v ? __ldg(pl[r] + idx) : PHI_PAD[r];
        }

        const float* wr = swm + fl * 9 * OT;
#pragma unroll
        for (int r = 0; r < 9; r++) {
            const ulonglong2* wv = (const ulonglong2*)(wr + r * OT);
#pragma unroll
            for (int p = 0; p < PX; p++) {
                float cf = (r & 1) ? cr[p][r >> 1].y : cr[p][r >> 1].x;
                long long cp = pk2(cf);
#pragma unroll
                for (int q = 0; q < OT / 4; q++) {
                    ulonglong2 a = wv[q];
                    acc[p][2 * q]     = ffma2(cp, (long long)a.x, acc[p][2 * q]);
                    acc[p][2 * q + 1] = ffma2(cp, (long long)a.y, acc[p][2 * q + 1]);
                }
            }
        }

        // advance (c, kh, kw)
        kw++;
        if (kw == K) {
            kw = 0;
            kh++;
            if (kh == K) { kh = 0; c++; }
        }
    }

    long long HW = (long long)Ho * Wo;
    float* ob = out + (long long)sl * B * OUT * HW;
#pragma unroll
    for (int p = 0; p < PX; p++) {
        if (!pv[p]) continue;
        int gp = blockIdx.x * T * PX + p * T + threadIdx.x;
        int b  = gp / (Ho * Wo);
        int rr = gp - b * Ho * Wo;
        float* op = ob + (long long)(b * OUT + ot * OT) * HW + rr;
#pragma unroll
        for (int k = 0; k < OT / 2; k++) {
            float2 v = upk2(acc[p][k]);
            op[(2 * k) * HW]     = v.x;
            op[(2 * k + 1) * HW] = v.y;
        }
    }
}

// ---------------------------------------------------------------------------
// sum NP partials -> relu -> 2x2 max pool -> phi (5 float2 planes)
// ---------------------------------------------------------------------------
template <int NP>
__global__ void maxpool_sum_phi(const float* __restrict__ in,
                                float2* __restrict__ phi,
                                int B, int C, int H, int W) {
    int Ho = H / 2, Wo = W / 2;
    int n = B * C * Ho * Wo;
    long long sz = (long long)B * C * H * W;
    int idx = blockIdx.x * blockDim.x + threadIdx.x;
    if (idx >= n) return;
    int wo = idx % Wo;
    int t  = idx / Wo;
    int ho = t % Ho;
    t /= Ho;
    int c = t % C;
    int b = t / C;
    long long base = ((long long)(b * C + c) * H + ho * 2) * W + wo * 2;
    float v[4] = {0.f, 0.f, 0.f, 0.f};
#pragma unroll
    for (int p = 0; p < NP; p++) {
        const float* ip = in + p * sz + base;
        v[0] += ip[0];
        v[1] += ip[1];
        v[2] += ip[W];
        v[3] += ip[W + 1];
    }
    float m = fmaxf(fmaxf(fmaxf(v[0], v[1]), fmaxf(v[2], v[3])), 0.0f);
    float cf[9];
    eval9(m, cf);
    store_phi_pairs(phi, n, idx, cf);
}

template <int NP>
__global__ void reduce_relu(const float* __restrict__ in, float* __restrict__ out,
                            int n) {
    int idx = blockIdx.x * blockDim.x + threadIdx.x;
    if (idx >= n) return;
    float s = 0.0f;
#pragma unroll
    for (int p = 0; p < NP; p++) s += in[(long long)p * n + idx];
    out[idx] = fmaxf(s, 0.0f);
}

// ---------------------------------------------------------------------------
// Head: mean(7x7) -> KAN linear 64 -> 200.  8 blocks x 25 outputs.
// ---------------------------------------------------------------------------
__global__ void classifier_kernel(const float* __restrict__ act,
                                  const float* __restrict__ wp,
                                  float* __restrict__ out) {
    __shared__ float mean[512];
    __shared__ float cs[512 * 5];
    __shared__ int   cr[512 * 4];
    int tid = threadIdx.x;
    int ot  = blockIdx.x;

    for (int e = tid; e < 512; e += 256) {
        const float* p = act + e * 49;
        float s = 0.0f;
#pragma unroll
        for (int i = 0; i < 49; i++) s += p[i];
        mean[e] = s * (1.0f / 49.0f);
    }
    __syncthreads();
    for (int e = tid; e < 512; e += 256) {
        float c0, w4[4];
        int   rw[4];
        eval5(mean[e], c0, w4, rw);
        cs[e * 5 + 0] = c0;
#pragma unroll
        for (int t = 0; t < 4; t++) {
            cs[e * 5 + 1 + t] = w4[t];
            cr[e * 4 + t]     = rw[t];
        }
    }
    __syncthreads();
    if (tid < 200) {
        int b = tid / 25;
        int o = ot * 25 + tid % 25;
        float acc = 0.0f;
#pragma unroll 4
        for (int i = 0; i < 64; i++) {
            int e = b * 64 + i;
            const float* cp = &cs[e * 5];
            const int*   rp = &cr[e * 4];
            const float* wr = wp + i * 9 * 200 + o;
            acc = fmaf(cp[0], wr[0], acc);
            acc = fmaf(cp[1], wr[rp[0] * 200], acc);
            acc = fmaf(cp[2], wr[rp[1] * 200], acc);
            acc = fmaf(cp[3], wr[rp[2] * 200], acc);
            acc = fmaf(cp[4], wr[rp[3] * 200], acc);
        }
        out[b * 200 + o] = acc;
    }
}

// ---------------------------------------------------------------------------
// Host launcher
// ---------------------------------------------------------------------------
static void* sym_addr(const void* symbol) {
    void* p = nullptr;
    cudaGetSymbolAddress(&p, symbol);
    return p;
}

extern "C" void kernel_launch(void* const* d_in, const int* in_sizes, int n_in,
                              void* d_out, int out_size) {
    const float* x   = (const float*)d_in[0];
    const float* bw0 = (const float*)d_in[1];
    const float* sw0 = (const float*)d_in[2];
    const float* sc0 = (const float*)d_in[3];
    const float* bw1 = (const float*)d_in[4];
    const float* sw1 = (const float*)d_in[5];
    const float* sc1 = (const float*)d_in[6];
    const float* bw2 = (const float*)d_in[7];
    const float* sw2 = (const float*)d_in[8];
    const float* sc2 = (const float*)d_in[9];
    const float* bwc = (const float*)d_in[10];
    const float* swc = (const float*)d_in[11];
    const float* scc = (const float*)d_in[12];
    float* out = (float*)d_out;

    float*  wp0   = (float*)sym_addr(g_wp0);
    float*  wp1   = (float*)sym_addr(g_wp1);
    float*  wp2   = (float*)sym_addr(g_wp2);
    float*  wpc   = (float*)sym_addr(g_wpc);
    float2* phi0  = (float2*)sym_addr(g_phi0);
    float*  part0 = (float*)sym_addr(g_part0);
    float2* phi1  = (float2*)sym_addr(g_phi1);
    float*  part1 = (float*)sym_addr(g_part1);
    float2* phi2  = (float2*)sym_addr(g_phi2);
    float*  part2 = (float*)sym_addr(g_part2);
    float*  a2    = (float*)sym_addr(g_a2);

    {
        int total = N0P + N1P + N2P + NCP;
        pack_all<<<(total + 255) / 256, 256>>>(bw0, sw0, sc0, bw1, sw1, sc1,
                                               bw2, sw2, sc2, bwc, swc, scc,
                                               wp0, wp1, wp2, wpc);
    }

    // ---- L0: phi -> conv (196x3 blocks, PX=4) -> pool+phi ----
    phi_eval<<<(NPIX0 + 255) / 256, 256>>>(x, phi0, NPIX0);
    {
        auto k = kan_conv_g<3, 7, 2, 3, 16, 16, 4, 128, 49>;
        dim3 grid(196, 3);
        k<<<grid, 128>>>(phi0, wp0, part0, 8, 224, 224, 112, 112);
        maxpool_sum_phi<3><<<(NPIX1 + 255) / 256, 256>>>(part0, phi1, 8, 16, 112, 112);
    }
    // ---- L1: 12 K-slices x 2 o-tiles -> pool+phi ----
    {
        auto k = kan_conv_g<16, 3, 2, 1, 32, 16, 4, 128, 12>;
        dim3 grid(13, 24);
        k<<<grid, 128>>>(phi1, wp1, part1, 8, 56, 56, 28, 28);
        maxpool_sum_phi<12><<<(NPIX2 + 255) / 256, 256>>>(part1, phi2, 8, 32, 28, 28);
    }
    // ---- L2: 36 K-slices x 4 o-tiles -> reduce_relu ----
    {
        auto k = kan_conv_g<32, 3, 2, 1, 64, 16, 1, 128, 8>;
        dim3 grid(4, 144);
        k<<<grid, 128>>>(phi2, wp2, part2, 8, 14, 14, 7, 7);
        reduce_relu<36><<<(8 * 64 * 7 * 7 + 255) / 256, 256>>>(part2, a2, 8 * 64 * 7 * 7);
    }
    classifier_kernel<<<8, 256>>>(a2, wpc, out);

    (void)in_sizes; (void)n_in; (void)out_size;
}

// round 12
// speedup vs baseline: 1.4080x; 1.0269x over previous
#include <cuda_runtime.h>
#include <math.h>

// ---------------------------------------------------------------------------
// KANConvNet round 11: spatially padded phi buffers (halo = eval9(0)) so the
// conv inner loop has NO bounds checks / SELs; block-uniform incremental tap
// offset. Otherwise identical to the 191.5us R10 baseline.
//   phi layout: [5 float2 planes][B*CIN*HP*WP], HP=H+2P, WP=W+2P.
// ---------------------------------------------------------------------------

// L0 input (x): 8x3x224x224, pad 3 -> 230x230
#define HP0 230
#define NPAD0 (8 * 3 * HP0 * HP0)
// L1 input (pooled 56x56), pad 1 -> 58x58
#define HP1 58
#define NPAD1 (8 * 16 * HP1 * HP1)
// L2 input (pooled 14x14), pad 1 -> 16x16
#define HP2 16
#define NPAD2 (8 * 32 * HP2 * HP2)

__device__ float g_wp0[147 * 9 * 16];
__device__ float g_wp1[144 * 9 * 32];
__device__ float g_wp2[288 * 9 * 64];
__device__ float g_wpc[64  * 9 * 200];

__device__ float2 g_phi0[5 * NPAD0];
__device__ float  g_part0[3 * 8 * 16 * 112 * 112];
__device__ float2 g_phi1[5 * NPAD1];
__device__ float  g_part1[12 * 8 * 32 * 28 * 28];
__device__ float2 g_phi2[5 * NPAD2];
__device__ float  g_part2[36 * 8 * 64 * 7 * 7];
__device__ float  g_a2[8 * 64 * 7 * 7];

#define N0P (147 * 9 * 16)
#define N1P (144 * 9 * 32)
#define N2P (288 * 9 * 64)
#define NCP (64  * 9 * 200)

// ---------------- packed f32x2 helpers ----------------
__device__ __forceinline__ long long pk2(float a) {
    long long r;
    asm("mov.b64 %0, {%1, %1};" : "=l"(r) : "f"(a));
    return r;
}
__device__ __forceinline__ long long ffma2(long long a, long long b, long long c) {
    long long d;
    asm("fma.rn.f32x2 %0, %1, %2, %3;" : "=l"(d) : "l"(a), "l"(b), "l"(c));
    return d;
}
__device__ __forceinline__ float2 upk2(long long a) {
    float x, y;
    asm("mov.b64 {%0, %1}, %2;" : "=f"(x), "=f"(y) : "l"(a));
    return make_float2(x, y);
}

// ---------------- dense 9-coefficient evaluation ----------------
__device__ __forceinline__ void eval9(float x, float* c) {
    float sig = 1.0f / (1.0f + __expf(-x));
    c[0] = x * sig;
    float t  = fmaf(x, 2.5f, 5.5f);          // (x + 2.2) / 0.4
    float mf = floorf(t);
    bool inr = (mf >= 0.0f) && (mf <= 10.0f);
    mf = fminf(fmaxf(mf, 0.0f), 10.0f);
    float u  = t - mf;
    float u2 = u * u;
    float u3 = u2 * u;
    float om = 1.0f - u;
    const float s6 = 1.0f / 6.0f;
    float w0 = s6 * om * om * om;
    float w1 = s6 * fmaf(3.0f, u3, fmaf(-6.0f, u2, 4.0f));
    float w2 = s6 * fmaf(-3.0f, u3, fmaf(3.0f, u2, fmaf(3.0f, u, 1.0f)));
    float w3 = s6 * u3;
    int m = (int)mf;
#pragma unroll
    for (int r = 1; r < 9; r++) {
        int tt = (r - 1) - (m - 3);
        float cv = 0.0f;
        cv = (tt == 0) ? w0 : cv;
        cv = (tt == 1) ? w1 : cv;
        cv = (tt == 2) ? w2 : cv;
        cv = (tt == 3) ? w3 : cv;
        c[r] = inr ? cv : 0.0f;
    }
}

// eval5 (sparse) for the classifier head
__device__ __forceinline__ void eval5(float x, float& c0, float* w, int* r) {
    float sig = 1.0f / (1.0f + __expf(-x));
    c0 = x * sig;
    float t  = fmaf(x, 2.5f, 5.5f);
    float mf = floorf(t);
    bool inr = (mf >= 0.0f) && (mf <= 10.0f);
    mf = fminf(fmaxf(mf, 0.0f), 10.0f);
    float u  = t - mf;
    float u2 = u * u;
    float u3 = u2 * u;
    float om = 1.0f - u;
    const float s6 = 1.0f / 6.0f;
    float a0 = s6 * om * om * om;
    float a1 = s6 * fmaf(3.0f, u3, fmaf(-6.0f, u2, 4.0f));
    float a2 = s6 * fmaf(-3.0f, u3, fmaf(3.0f, u2, fmaf(3.0f, u, 1.0f)));
    float a3 = s6 * u3;
    int m = (int)mf;
    w[0] = (inr && m >= 3)            ? a0 : 0.0f;
    w[1] = (inr && m >= 2 && m <= 9)  ? a1 : 0.0f;
    w[2] = (inr && m >= 1 && m <= 8)  ? a2 : 0.0f;
    w[3] = (inr && m <= 7)            ? a3 : 0.0f;
#pragma unroll
    for (int t4 = 0; t4 < 4; t4++) {
        int j = m - 3 + t4;
        j = j < 0 ? 0 : (j > 7 ? 7 : j);
        r[t4] = 1 + j;
    }
}

// store 9 coefficients as 5 float2 planes (plane stride n)
__device__ __forceinline__ void store_phi_pairs(float2* __restrict__ phi,
                                                long long n, long long i,
                                                const float* c) {
    phi[0 * n + i] = make_float2(c[0], c[1]);
    phi[1 * n + i] = make_float2(c[2], c[3]);
    phi[2 * n + i] = make_float2(c[4], c[5]);
    phi[3 * n + i] = make_float2(c[6], c[7]);
    phi[4 * n + i] = make_float2(c[8], 0.0f);
}

// ---------------- phi precompute into PADDED layout (layer-0 input) --------
__global__ void phi_eval_pad(const float* __restrict__ x, float2* __restrict__ phi,
                             int B, int C, int H, int W, int P, int npad) {
    int i = blockIdx.x * blockDim.x + threadIdx.x;
    if (i >= npad) return;
    int WP = W + 2 * P, HPd = H + 2 * P;
    int wp_ = i % WP;
    int t   = i / WP;
    int hp_ = t % HPd;
    t /= HPd;
    int c = t % C;
    int b = t / C;
    int hin = hp_ - P, win = wp_ - P;
    float xv = 0.0f;
    if (hin >= 0 && hin < H && win >= 0 && win < W)
        xv = x[((b * C + c) * H + hin) * W + win];
    float cf[9];
    eval9(xv, cf);
    store_phi_pairs(phi, npad, i, cf);
}

// ---------------- merged weight packing ----------------
__device__ __forceinline__ void pack_one(int idx,
                                         const float* __restrict__ bw,
                                         const float* __restrict__ sw,
                                         const float* __restrict__ sc,
                                         float* __restrict__ wp,
                                         int OUT, int IN) {
    int i   = idx / (9 * OUT);
    int rem = idx - i * 9 * OUT;
    int r   = rem / OUT;
    int o   = rem - r * OUT;
    int oi  = o * IN + i;
    float v = (r == 0) ? bw[oi] : sw[oi * 8 + (r - 1)] * sc[oi];
    wp[idx] = v;
}

__global__ void pack_all(const float* bw0, const float* sw0, const float* sc0,
                         const float* bw1, const float* sw1, const float* sc1,
                         const float* bw2, const float* sw2, const float* sc2,
                         const float* bwc, const float* swc, const float* scc,
                         float* wp0, float* wp1, float* wp2, float* wpc) {
    int idx = blockIdx.x * blockDim.x + threadIdx.x;
    if (idx < N0P) { pack_one(idx, bw0, sw0, sc0, wp0, 16, 147); return; }
    idx -= N0P;
    if (idx < N1P) { pack_one(idx, bw1, sw1, sc1, wp1, 32, 144); return; }
    idx -= N1P;
    if (idx < N2P) { pack_one(idx, bw2, sw2, sc2, wp2, 64, 288); return; }
    idx -= N2P;
    if (idx < NCP) { pack_one(idx, bwc, swc, scc, wpc, 200, 64); }
}

// ---------------------------------------------------------------------------
// Dense gather-GEMM conv over PADDED phi: no bounds checks in the f-loop.
// HPd/WPd: padded input dims. Position p base offset includes the halo shift.
// ---------------------------------------------------------------------------
template <int CIN, int K, int S, int OUT, int OT, int PX, int T, int FSL>
__global__ void __launch_bounds__(T, 3)
kan_conv_g(const float2* __restrict__ phi,  // [5][B*CIN*HPd*WPd]
           const float* __restrict__ wp,    // [F][9][OUT]
           float* __restrict__ out,
           int B, int HPd, int WPd, int Ho, int Wo) {
    __shared__ float swm[FSL * 9 * OT];
    const int NOT   = OUT / OT;
    const int sl    = blockIdx.y / NOT;
    const int ot    = blockIdx.y - sl * NOT;
    const int NPIXP = B * CIN * HPd * WPd;

    for (int idx = threadIdx.x; idx < FSL * 9 * OT; idx += T) {
        int f   = idx / (9 * OT);
        int rem = idx - f * 9 * OT;
        int r   = rem / OT;
        int o   = rem - r * OT;
        swm[idx] = wp[((sl * FSL + f) * 9 + r) * OUT + ot * OT + o];
    }
    __syncthreads();

    const float2* pl[5];
#pragma unroll
    for (int r = 0; r < 5; r++) pl[r] = phi + (long long)r * NPIXP;

    const int N = B * Ho * Wo;
    int  off[PX];
    bool pv[PX];
#pragma unroll
    for (int p = 0; p < PX; p++) {
        int gp = blockIdx.x * T * PX + p * T + threadIdx.x;
        pv[p]  = gp < N;
        int g  = pv[p] ? gp : 0;
        int b  = g / (Ho * Wo);
        int rr = g - b * Ho * Wo;
        int ho = rr / Wo;
        int wo = rr - ho * Wo;
        off[p] = b * CIN * HPd * WPd + (ho * S) * WPd + wo * S;
    }

    long long acc[PX][OT / 2];
#pragma unroll
    for (int p = 0; p < PX; p++)
#pragma unroll
        for (int k = 0; k < OT / 2; k++) acc[p][k] = 0LL;

    // block-uniform incremental tap offset
    int f0 = sl * FSL;
    int c  = f0 / (K * K);
    int r0 = f0 - c * K * K;
    int kh = r0 / K;
    int kw = r0 - kh * K;
    int uofs = (c * HPd + kh) * WPd + kw;

#pragma unroll 1
    for (int fl = 0; fl < FSL; fl++) {
        float2 cr[PX][5];
#pragma unroll
        for (int p = 0; p < PX; p++) {
            int idx = off[p] + uofs;
#pragma unroll
            for (int r = 0; r < 5; r++)
                cr[p][r] = __ldg(pl[r] + idx);
        }

        const float* wr = swm + fl * 9 * OT;
#pragma unroll
        for (int r = 0; r < 9; r++) {
            const ulonglong2* wv = (const ulonglong2*)(wr + r * OT);
#pragma unroll
            for (int p = 0; p < PX; p++) {
                float cf = (r & 1) ? cr[p][r >> 1].y : cr[p][r >> 1].x;
                long long cp = pk2(cf);
#pragma unroll
                for (int q = 0; q < OT / 4; q++) {
                    ulonglong2 a = wv[q];
                    acc[p][2 * q]     = ffma2(cp, (long long)a.x, acc[p][2 * q]);
                    acc[p][2 * q + 1] = ffma2(cp, (long long)a.y, acc[p][2 * q + 1]);
                }
            }
        }

        kw++; uofs++;
        if (kw == K) {
            kw = 0; kh++; uofs += WPd - K;
            if (kh == K) { kh = 0; c++; uofs += (HPd - K) * WPd; }
        }
    }

    long long HW = (long long)Ho * Wo;
    float* ob = out + (long long)sl * B * OUT * HW;
#pragma unroll
    for (int p = 0; p < PX; p++) {
        if (!pv[p]) continue;
        int gp = blockIdx.x * T * PX + p * T + threadIdx.x;
        int b  = gp / (Ho * Wo);
        int rr = gp - b * Ho * Wo;
        float* op = ob + (long long)(b * OUT + ot * OT) * HW + rr;
#pragma unroll
        for (int k = 0; k < OT / 2; k++) {
            float2 v = upk2(acc[p][k]);
            op[(2 * k) * HW]     = v.x;
            op[(2 * k + 1) * HW] = v.y;
        }
    }
}

// ---------------------------------------------------------------------------
// sum NP partials -> relu -> 2x2 max pool -> phi into PADDED next-layer layout
// Grid covers padded cells; halo cells get eval9(0).
// ---------------------------------------------------------------------------
template <int NP>
__global__ void maxpool_sum_phi_pad(const float* __restrict__ in,  // partials over (B,C,H,W)
                                    float2* __restrict__ phi,
                                    int B, int C, int H, int W,    // pre-pool dims
                                    int P, int npad) {
    int Ho = H / 2, Wo = W / 2;
    int WP = Wo + 2 * P, HPd = Ho + 2 * P;
    long long sz = (long long)B * C * H * W;
    int i = blockIdx.x * blockDim.x + threadIdx.x;
    if (i >= npad) return;
    int wp_ = i % WP;
    int t   = i / WP;
    int hp_ = t % HPd;
    t /= HPd;
    int c = t % C;
    int b = t / C;
    int ho = hp_ - P, wo = wp_ - P;
    float m = 0.0f;
    if (ho >= 0 && ho < Ho && wo >= 0 && wo < Wo) {
        long long base = ((long long)(b * C + c) * H + ho * 2) * W + wo * 2;
        float v[4] = {0.f, 0.f, 0.f, 0.f};
#pragma unroll
        for (int p = 0; p < NP; p++) {
            const float* ip = in + p * sz + base;
            v[0] += ip[0];
            v[1] += ip[1];
            v[2] += ip[W];
            v[3] += ip[W + 1];
        }
        m = fmaxf(fmaxf(fmaxf(v[0], v[1]), fmaxf(v[2], v[3])), 0.0f);
    }
    float cf[9];
    eval9(m, cf);
    store_phi_pairs(phi, npad, i, cf);
}

template <int NP>
__global__ void reduce_relu(const float* __restrict__ in, float* __restrict__ out,
                            int n) {
    int idx = blockIdx.x * blockDim.x + threadIdx.x;
    if (idx >= n) return;
    float s = 0.0f;
#pragma unroll
    for (int p = 0; p < NP; p++) s += in[(long long)p * n + idx];
    out[idx] = fmaxf(s, 0.0f);
}

// ---------------------------------------------------------------------------
// Head: mean(7x7) -> KAN linear 64 -> 200.  8 blocks x 25 outputs.
// ---------------------------------------------------------------------------
__global__ void classifier_kernel(const float* __restrict__ act,
                                  const float* __restrict__ wp,
                                  float* __restrict__ out) {
    __shared__ float mean[512];
    __shared__ float cs[512 * 5];
    __shared__ int   cr[512 * 4];
    int tid = threadIdx.x;
    int ot  = blockIdx.x;

    for (int e = tid; e < 512; e += 256) {
        const float* p = act + e * 49;
        float s = 0.0f;
#pragma unroll
        for (int i = 0; i < 49; i++) s += p[i];
        mean[e] = s * (1.0f / 49.0f);
    }
    __syncthreads();
    for (int e = tid; e < 512; e += 256) {
        float c0, w4[4];
        int   rw[4];
        eval5(mean[e], c0, w4, rw);
        cs[e * 5 + 0] = c0;
#pragma unroll
        for (int t = 0; t < 4; t++) {
            cs[e * 5 + 1 + t] = w4[t];
            cr[e * 4 + t]     = rw[t];
        }
    }
    __syncthreads();
    if (tid < 200) {
        int b = tid / 25;
        int o = ot * 25 + tid % 25;
        float acc = 0.0f;
#pragma unroll 4
        for (int i = 0; i < 64; i++) {
            int e = b * 64 + i;
            const float* cp = &cs[e * 5];
            const int*   rp = &cr[e * 4];
            const float* wr = wp + i * 9 * 200 + o;
            acc = fmaf(cp[0], wr[0], acc);
            acc = fmaf(cp[1], wr[rp[0] * 200], acc);
            acc = fmaf(cp[2], wr[rp[1] * 200], acc);
            acc = fmaf(cp[3], wr[rp[2] * 200], acc);
            acc = fmaf(cp[4], wr[rp[3] * 200], acc);
        }
        out[b * 200 + o] = acc;
    }
}

// ---------------------------------------------------------------------------
// Host launcher
// ---------------------------------------------------------------------------
static void* sym_addr(const void* symbol) {
    void* p = nullptr;
    cudaGetSymbolAddress(&p, symbol);
    return p;
}

extern "C" void kernel_launch(void* const* d_in, const int* in_sizes, int n_in,
                              void* d_out, int out_size) {
    const float* x   = (const float*)d_in[0];
    const float* bw0 = (const float*)d_in[1];
    const float* sw0 = (const float*)d_in[2];
    const float* sc0 = (const float*)d_in[3];
    const float* bw1 = (const float*)d_in[4];
    const float* sw1 = (const float*)d_in[5];
    const float* sc1 = (const float*)d_in[6];
    const float* bw2 = (const float*)d_in[7];
    const float* sw2 = (const float*)d_in[8];
    const float* sc2 = (const float*)d_in[9];
    const float* bwc = (const float*)d_in[10];
    const float* swc = (const float*)d_in[11];
    const float* scc = (const float*)d_in[12];
    float* out = (float*)d_out;

    float*  wp0   = (float*)sym_addr(g_wp0);
    float*  wp1   = (float*)sym_addr(g_wp1);
    float*  wp2   = (float*)sym_addr(g_wp2);
    float*  wpc   = (float*)sym_addr(g_wpc);
    float2* phi0  = (float2*)sym_addr(g_phi0);
    float*  part0 = (float*)sym_addr(g_part0);
    float2* phi1  = (float2*)sym_addr(g_phi1);
    float*  part1 = (float*)sym_addr(g_part1);
    float2* phi2  = (float2*)sym_addr(g_phi2);
    float*  part2 = (float*)sym_addr(g_part2);
    float*  a2    = (float*)sym_addr(g_a2);

    {
        int total = N0P + N1P + N2P + NCP;
        pack_all<<<(total + 255) / 256, 256>>>(bw0, sw0, sc0, bw1, sw1, sc1,
                                               bw2, sw2, sc2, bwc, swc, scc,
                                               wp0, wp1, wp2, wpc);
    }

    // ---- L0: padded phi -> conv (196x3 blocks, PX=4) -> pool+phi(padded) ----
    phi_eval_pad<<<(NPAD0 + 255) / 256, 256>>>(x, phi0, 8, 3, 224, 224, 3, NPAD0);
    {
        auto k = kan_conv_g<3, 7, 2, 16, 16, 4, 128, 49>;
        dim3 grid(196, 3);
        k<<<grid, 128>>>(phi0, wp0, part0, 8, HP0, HP0, 112, 112);
        maxpool_sum_phi_pad<3><<<(NPAD1 + 255) / 256, 256>>>(part0, phi1,
                                                             8, 16, 112, 112, 1, NPAD1);
    }
    // ---- L1: 12 K-slices x 2 o-tiles -> pool+phi(padded) ----
    {
        auto k = kan_conv_g<16, 3, 2, 32, 16, 4, 128, 12>;
        dim3 grid(13, 24);
        k<<<grid, 128>>>(phi1, wp1, part1, 8, HP1, HP1, 28, 28);
        maxpool_sum_phi_pad<12><<<(NPAD2 + 255) / 256, 256>>>(part1, phi2,
                                                              8, 32, 28, 28, 1, NPAD2);
    }
    // ---- L2: 36 K-slices x 4 o-tiles -> reduce_relu ----
    {
        auto k = kan_conv_g<32, 3, 2, 64, 16, 1, 128, 8>;
        dim3 grid(4, 144);
        k<<<grid, 128>>>(phi2, wp2, part2, 8, HP2, HP2, 7, 7);
        reduce_relu<36><<<(8 * 64 * 7 * 7 + 255) / 256, 256>>>(part2, a2, 8 * 64 * 7 * 7);
    }
    classifier_kernel<<<8, 256>>>(a2, wpc, out);

    (void)in_sizes; (void)n_in; (void)out_size;
}